// round 15
// baseline (speedup 1.0000x reference)
#include <cuda_runtime.h>
#include <math.h>

#define TRIALS 2048
#define CHUNK  4
#define NTHREADS 512
#define NWARPS (NTHREADS / 32)
#define NV (TRIALS * 2)

__device__ __forceinline__ float sel4(float t0, float t1, float t2, float t3, unsigned idx) {
    float a = (idx & 1u) ? t1 : t0;
    float b = (idx & 1u) ? t3 : t2;
    return (idx & 2u) ? b : a;
}

// 256-bit store (sm_100+): 8 consecutive floats, 32B-aligned
__device__ __forceinline__ void stg256(float* p, const float* r) {
    asm volatile("st.global.v8.f32 [%0], {%1,%2,%3,%4,%5,%6,%7,%8};"
        :: "l"(p), "f"(r[0]), "f"(r[1]), "f"(r[2]), "f"(r[3]),
                   "f"(r[4]), "f"(r[5]), "f"(r[6]), "f"(r[7])
        : "memory");
}

__global__ __launch_bounds__(NTHREADS, 4) void qv_kernel(
    const float* __restrict__ inp,
    const float* __restrict__ p_asr, const float* __restrict__ p_asu,
    const float* __restrict__ p_adr, const float* __restrict__ p_adu,
    const float* __restrict__ p_ksr, const float* __restrict__ p_ksu,
    const float* __restrict__ p_kdr, const float* __restrict__ p_kdu,
    float* __restrict__ out_v, float* __restrict__ out_diff, float* __restrict__ out_delta)
{
    __shared__ float s_wm[2][NWARPS], s_wc[2][NWARPS];

    const int tid  = threadIdx.x;
    const int lane = tid & 31, warp = tid >> 5;
    const int sess = blockIdx.x;

    // ---- coalesced load + binarize into one packed register (3 nibbles) ----
    const float4* g4 = (const float4*)(inp + (size_t)sess * (TRIALS * 3));
    const int wbase = warp * 96 + lane;
    unsigned pk = 0;
    #pragma unroll
    for (int j = 0; j < 3; ++j) {
        float4 q = g4[wbase + j * 32];
        unsigned nib = (q.x > 0.5f ? 1u : 0u) | (q.y > 0.5f ? 2u : 0u)
                     | (q.z > 0.5f ? 4u : 0u) | (q.w > 0.5f ? 8u : 0u);
        pk |= nib << (4 * j);
    }

    // ---- params: 4-entry tables indexed by (cl<<1)|o ----
    const float Asr = 1.f / (1.f + __expf(-p_asr[0]));
    const float Asu = 1.f / (1.f + __expf(-p_asu[0]));
    const float Adr = 1.f / (1.f + __expf(-p_adr[0]));
    const float Adu = 1.f / (1.f + __expf(-p_adu[0]));
    const float Ksr = p_ksr[0], Ksu = p_ksu[0], Kdr = p_kdr[0], Kdu = p_kdu[0];

    // ---- warp-internal transpose via shuffles: lane l needs words 3l+i ----
    unsigned bits = 0;
    #pragma unroll
    for (int i = 0; i < 3; ++i) {
        int w = 3 * lane + i;                         // 0..95
        unsigned f = __shfl_sync(0xffffffffu, pk, w & 31);
        bits |= ((f >> (4 * (w >> 5))) & 0xFu) << (4 * i);
    }
    // trial t (0..3): cl = bit 3t, o = bit 3t+2

    // ---- precompute per-trial 2-bit indices: idx = (cl<<1)|o ----
    unsigned ibits = 0;
    #pragma unroll
    for (int t = 0; t < CHUNK; ++t) {
        unsigned b3 = (bits >> (3 * t)) & 7u;
        ibits |= (((b3 & 1u) << 1) | (b3 >> 2)) << (2 * t);
    }

    // ---- phase 1: compose affine maps v' = m*v + c over my chunk ----
    float mL = 1.f, cL = 0.f, mR = 1.f, cR = 0.f;
    #pragma unroll
    for (int t = 0; t < CHUNK; ++t) {
        unsigned idx = (ibits >> (2 * t)) & 3u;
        unsigned jdx = idx ^ 2u;
        float aL = sel4(Adu, Adr, Asu, Asr, idx);
        float kL = sel4(Kdu, Kdr, Ksu, Ksr, idx);
        float aR = sel4(Adu, Adr, Asu, Asr, jdx);
        float kR = sel4(Kdu, Kdr, Ksu, Ksr, jdx);
        cL = fmaf(aL, kL - cL, cL);  mL = fmaf(-aL, mL, mL);
        cR = fmaf(aR, kR - cR, cR);  mR = fmaf(-aR, mR, mR);
    }

    // ---- warp-level inclusive scan (affine compose, earlier lane first) ----
    #pragma unroll
    for (int d = 1; d < 32; d <<= 1) {
        float pmL = __shfl_up_sync(0xffffffffu, mL, d);
        float pcL = __shfl_up_sync(0xffffffffu, cL, d);
        float pmR = __shfl_up_sync(0xffffffffu, mR, d);
        float pcR = __shfl_up_sync(0xffffffffu, cR, d);
        if (lane >= d) {
            cL = mL * pcL + cL;  mL = mL * pmL;
            cR = mR * pcR + cR;  mR = mR * pmR;
        }
    }
    if (lane == 31) {
        s_wm[0][warp] = mL; s_wc[0][warp] = cL;
        s_wm[1][warp] = mR; s_wc[1][warp] = cR;
    }

    __syncthreads();

    // ---- every thread composes its own warp-exclusive prefix (v0 = 0) ----
    // 4 independent scalar LDS per step: loads hoist, FMA chain stays short
    float pcl = 0.f, pcr = 0.f;
    #pragma unroll
    for (int w = 0; w < NWARPS - 1; ++w) {
        if (w < warp) {
            pcl = s_wm[0][w] * pcl + s_wc[0][w];
            pcr = s_wm[1][w] * pcr + s_wc[1][w];
        }
    }

    // end-of-chunk v for this lane; start-of-chunk = previous lane's end
    float veL = fmaf(mL, pcl, cL);
    float veR = fmaf(mR, pcr, cR);
    float vL = __shfl_up_sync(0xffffffffu, veL, 1);
    float vR = __shfl_up_sync(0xffffffffu, veR, 1);
    if (lane == 0) { vL = pcl; vR = pcr; }

    // ---- phase 2: compute all 24 outputs into registers, then batch stores ----
    float fv[8], fd[8], fe[8];
    #pragma unroll
    for (int t = 0; t < CHUNK; ++t) {
        unsigned idx = (ibits >> (2 * t)) & 3u;
        unsigned jdx = idx ^ 2u;
        float aL = sel4(Adu, Adr, Asu, Asr, idx);
        float kL = sel4(Kdu, Kdr, Ksu, Ksr, idx);
        float aR = sel4(Adu, Adr, Asu, Asr, jdx);
        float kR = sel4(Kdu, Kdr, Ksu, Ksr, jdx);
        float difL = kL - vL, difR = kR - vR;
        float dL = aL * difL, dR = aR * difR;
        fd[2 * t + 0] = difL;  fd[2 * t + 1] = difR;
        fe[2 * t + 0] = dL;    fe[2 * t + 1] = dR;
        vL += dL;  vR += dR;
        fv[2 * t + 0] = vL;    fv[2 * t + 1] = vR;
    }

    const size_t ob = (size_t)sess * NV + (size_t)tid * (CHUNK * 2);
    stg256(out_v + ob,     fv);
    stg256(out_diff + ob,  fd);
    stg256(out_delta + ob, fe);
}

extern "C" void kernel_launch(void* const* d_in, const int* in_sizes, int n_in,
                              void* d_out, int out_size)
{
    const float* inp = (const float*)d_in[0];
    float* out = (float*)d_out;
    const int n_sess = in_sizes[0] / (TRIALS * 3);
    const size_t per = (size_t)n_sess * TRIALS * 2;

    qv_kernel<<<n_sess, NTHREADS>>>(
        inp,
        (const float*)d_in[1], (const float*)d_in[2],
        (const float*)d_in[3], (const float*)d_in[4],
        (const float*)d_in[5], (const float*)d_in[6],
        (const float*)d_in[7], (const float*)d_in[8],
        out, out + per, out + 2 * per);
}

// round 16
// speedup vs baseline: 1.0112x; 1.0112x over previous
#include <cuda_runtime.h>
#include <math.h>

#define TRIALS 2048
#define CHUNK  4
#define NTHREADS 512
#define NWARPS (NTHREADS / 32)
#define NV (TRIALS * 2)

__device__ __forceinline__ float sel4(float t0, float t1, float t2, float t3, unsigned idx) {
    float a = (idx & 1u) ? t1 : t0;
    float b = (idx & 1u) ? t3 : t2;
    return (idx & 2u) ? b : a;
}

// 256-bit store (sm_100+): 8 consecutive floats, 32B-aligned
__device__ __forceinline__ void stg256(float* p, const float* r) {
    asm volatile("st.global.v8.f32 [%0], {%1,%2,%3,%4,%5,%6,%7,%8};"
        :: "l"(p), "f"(r[0]), "f"(r[1]), "f"(r[2]), "f"(r[3]),
                   "f"(r[4]), "f"(r[5]), "f"(r[6]), "f"(r[7])
        : "memory");
}

__global__ __launch_bounds__(NTHREADS, 4) void qv_kernel(
    const float* __restrict__ inp,
    const float* __restrict__ p_asr, const float* __restrict__ p_asu,
    const float* __restrict__ p_adr, const float* __restrict__ p_adu,
    const float* __restrict__ p_ksr, const float* __restrict__ p_ksu,
    const float* __restrict__ p_kdr, const float* __restrict__ p_kdu,
    float* __restrict__ out_v, float* __restrict__ out_diff, float* __restrict__ out_delta)
{
    __shared__ float s_wm[2][NWARPS], s_wc[2][NWARPS];

    const int tid  = threadIdx.x;
    const int lane = tid & 31, warp = tid >> 5;
    const int sess = blockIdx.x;

    // ---- coalesced load + binarize into one packed register (3 nibbles) ----
    const float4* g4 = (const float4*)(inp + (size_t)sess * (TRIALS * 3));
    const int wbase = warp * 96 + lane;
    unsigned pk = 0;
    #pragma unroll
    for (int j = 0; j < 3; ++j) {
        float4 q = g4[wbase + j * 32];
        unsigned nib = (q.x > 0.5f ? 1u : 0u) | (q.y > 0.5f ? 2u : 0u)
                     | (q.z > 0.5f ? 4u : 0u) | (q.w > 0.5f ? 8u : 0u);
        pk |= nib << (4 * j);
    }

    // ---- params: 4-entry tables indexed by (cl<<1)|o ----
    const float Asr = 1.f / (1.f + __expf(-p_asr[0]));
    const float Asu = 1.f / (1.f + __expf(-p_asu[0]));
    const float Adr = 1.f / (1.f + __expf(-p_adr[0]));
    const float Adu = 1.f / (1.f + __expf(-p_adu[0]));
    const float Ksr = p_ksr[0], Ksu = p_ksu[0], Kdr = p_kdr[0], Kdu = p_kdu[0];

    // ---- warp-internal transpose via shuffles: lane l needs words 3l+i ----
    unsigned bits = 0;
    #pragma unroll
    for (int i = 0; i < 3; ++i) {
        int w = 3 * lane + i;                         // 0..95
        unsigned f = __shfl_sync(0xffffffffu, pk, w & 31);
        bits |= ((f >> (4 * (w >> 5))) & 0xFu) << (4 * i);
    }
    // trial t (0..3): cl = bit 3t, o = bit 3t+2

    // ---- precompute per-trial 2-bit indices: idx = (cl<<1)|o ----
    unsigned ibits = 0;
    #pragma unroll
    for (int t = 0; t < CHUNK; ++t) {
        unsigned b3 = (bits >> (3 * t)) & 7u;
        ibits |= (((b3 & 1u) << 1) | (b3 >> 2)) << (2 * t);
    }

    // ---- phase 1: compose affine maps v' = m*v + c over my chunk ----
    float mL = 1.f, cL = 0.f, mR = 1.f, cR = 0.f;
    #pragma unroll
    for (int t = 0; t < CHUNK; ++t) {
        unsigned idx = (ibits >> (2 * t)) & 3u;
        unsigned jdx = idx ^ 2u;
        float aL = sel4(Adu, Adr, Asu, Asr, idx);
        float kL = sel4(Kdu, Kdr, Ksu, Ksr, idx);
        float aR = sel4(Adu, Adr, Asu, Asr, jdx);
        float kR = sel4(Kdu, Kdr, Ksu, Ksr, jdx);
        cL = fmaf(aL, kL - cL, cL);  mL = fmaf(-aL, mL, mL);
        cR = fmaf(aR, kR - cR, cR);  mR = fmaf(-aR, mR, mR);
    }

    // ---- warp-level inclusive scan (affine compose, earlier lane first) ----
    #pragma unroll
    for (int d = 1; d < 32; d <<= 1) {
        float pmL = __shfl_up_sync(0xffffffffu, mL, d);
        float pcL = __shfl_up_sync(0xffffffffu, cL, d);
        float pmR = __shfl_up_sync(0xffffffffu, mR, d);
        float pcR = __shfl_up_sync(0xffffffffu, cR, d);
        if (lane >= d) {
            cL = mL * pcL + cL;  mL = mL * pmL;
            cR = mR * pcR + cR;  mR = mR * pmR;
        }
    }
    if (lane == 31) {
        s_wm[0][warp] = mL; s_wc[0][warp] = cL;
        s_wm[1][warp] = mR; s_wc[1][warp] = cR;
    }

    __syncthreads();

    // ---- every thread composes its own warp-exclusive prefix (v0 = 0) ----
    // 4 independent scalar LDS per step: loads hoist, FMA chain stays short
    float pcl = 0.f, pcr = 0.f;
    #pragma unroll
    for (int w = 0; w < NWARPS - 1; ++w) {
        if (w < warp) {
            pcl = s_wm[0][w] * pcl + s_wc[0][w];
            pcr = s_wm[1][w] * pcr + s_wc[1][w];
        }
    }

    // end-of-chunk v for this lane; start-of-chunk = previous lane's end
    float veL = fmaf(mL, pcl, cL);
    float veR = fmaf(mR, pcr, cR);
    float vL = __shfl_up_sync(0xffffffffu, veL, 1);
    float vR = __shfl_up_sync(0xffffffffu, veR, 1);
    if (lane == 0) { vL = pcl; vR = pcr; }

    // ---- phase 2: compute all 24 outputs into registers, then batch stores ----
    float fv[8], fd[8], fe[8];
    #pragma unroll
    for (int t = 0; t < CHUNK; ++t) {
        unsigned idx = (ibits >> (2 * t)) & 3u;
        unsigned jdx = idx ^ 2u;
        float aL = sel4(Adu, Adr, Asu, Asr, idx);
        float kL = sel4(Kdu, Kdr, Ksu, Ksr, idx);
        float aR = sel4(Adu, Adr, Asu, Asr, jdx);
        float kR = sel4(Kdu, Kdr, Ksu, Ksr, jdx);
        float difL = kL - vL, difR = kR - vR;
        float dL = aL * difL, dR = aR * difR;
        fd[2 * t + 0] = difL;  fd[2 * t + 1] = difR;
        fe[2 * t + 0] = dL;    fe[2 * t + 1] = dR;
        vL += dL;  vR += dR;
        fv[2 * t + 0] = vL;    fv[2 * t + 1] = vR;
    }

    const size_t ob = (size_t)sess * NV + (size_t)tid * (CHUNK * 2);
    stg256(out_v + ob,     fv);
    stg256(out_diff + ob,  fd);
    stg256(out_delta + ob, fe);
}

extern "C" void kernel_launch(void* const* d_in, const int* in_sizes, int n_in,
                              void* d_out, int out_size)
{
    const float* inp = (const float*)d_in[0];
    float* out = (float*)d_out;
    const int n_sess = in_sizes[0] / (TRIALS * 3);
    const size_t per = (size_t)n_sess * TRIALS * 2;

    qv_kernel<<<n_sess, NTHREADS>>>(
        inp,
        (const float*)d_in[1], (const float*)d_in[2],
        (const float*)d_in[3], (const float*)d_in[4],
        (const float*)d_in[5], (const float*)d_in[6],
        (const float*)d_in[7], (const float*)d_in[8],
        out, out + per, out + 2 * per);
}

// round 17
// speedup vs baseline: 1.0119x; 1.0006x over previous
#include <cuda_runtime.h>
#include <math.h>

#define TRIALS 2048
#define CHUNK  4
#define NTHREADS 512
#define NWARPS (NTHREADS / 32)
#define NV (TRIALS * 2)

__device__ __forceinline__ float sel4(float t0, float t1, float t2, float t3, unsigned idx) {
    float a = (idx & 1u) ? t1 : t0;
    float b = (idx & 1u) ? t3 : t2;
    return (idx & 2u) ? b : a;
}

// 256-bit store (sm_100+): 8 consecutive floats, 32B-aligned
__device__ __forceinline__ void stg256(float* p, const float* r) {
    asm volatile("st.global.v8.f32 [%0], {%1,%2,%3,%4,%5,%6,%7,%8};"
        :: "l"(p), "f"(r[0]), "f"(r[1]), "f"(r[2]), "f"(r[3]),
                   "f"(r[4]), "f"(r[5]), "f"(r[6]), "f"(r[7])
        : "memory");
}

__global__ __launch_bounds__(NTHREADS, 4) void qv_kernel(
    const float* __restrict__ inp,
    const float* __restrict__ p_asr, const float* __restrict__ p_asu,
    const float* __restrict__ p_adr, const float* __restrict__ p_adu,
    const float* __restrict__ p_ksr, const float* __restrict__ p_ksu,
    const float* __restrict__ p_kdr, const float* __restrict__ p_kdu,
    float* __restrict__ out_v, float* __restrict__ out_diff, float* __restrict__ out_delta)
{
    __shared__ float s_wm[2][NWARPS], s_wc[2][NWARPS];

    const int tid  = threadIdx.x;
    const int lane = tid & 31, warp = tid >> 5;
    const int sess = blockIdx.x;

    // ---- coalesced load + binarize into one packed register (3 nibbles) ----
    const float4* g4 = (const float4*)(inp + (size_t)sess * (TRIALS * 3));
    const int wbase = warp * 96 + lane;
    unsigned pk = 0;
    #pragma unroll
    for (int j = 0; j < 3; ++j) {
        float4 q = g4[wbase + j * 32];
        unsigned nib = (q.x > 0.5f ? 1u : 0u) | (q.y > 0.5f ? 2u : 0u)
                     | (q.z > 0.5f ? 4u : 0u) | (q.w > 0.5f ? 8u : 0u);
        pk |= nib << (4 * j);
    }

    // ---- params: 4-entry tables indexed by (cl<<1)|o ----
    const float Asr = 1.f / (1.f + __expf(-p_asr[0]));
    const float Asu = 1.f / (1.f + __expf(-p_asu[0]));
    const float Adr = 1.f / (1.f + __expf(-p_adr[0]));
    const float Adu = 1.f / (1.f + __expf(-p_adu[0]));
    const float Ksr = p_ksr[0], Ksu = p_ksu[0], Kdr = p_kdr[0], Kdu = p_kdu[0];

    // ---- warp-internal transpose via shuffles: lane l needs words 3l+i ----
    unsigned bits = 0;
    #pragma unroll
    for (int i = 0; i < 3; ++i) {
        int w = 3 * lane + i;                         // 0..95
        unsigned f = __shfl_sync(0xffffffffu, pk, w & 31);
        bits |= ((f >> (4 * (w >> 5))) & 0xFu) << (4 * i);
    }
    // trial t (0..3): cl = bit 3t, o = bit 3t+2

    // ---- precompute per-trial 2-bit indices: idx = (cl<<1)|o ----
    unsigned ibits = 0;
    #pragma unroll
    for (int t = 0; t < CHUNK; ++t) {
        unsigned b3 = (bits >> (3 * t)) & 7u;
        ibits |= (((b3 & 1u) << 1) | (b3 >> 2)) << (2 * t);
    }

    // ---- phase 1: compose affine maps v' = m*v + c over my chunk ----
    float mL = 1.f, cL = 0.f, mR = 1.f, cR = 0.f;
    #pragma unroll
    for (int t = 0; t < CHUNK; ++t) {
        unsigned idx = (ibits >> (2 * t)) & 3u;
        unsigned jdx = idx ^ 2u;
        float aL = sel4(Adu, Adr, Asu, Asr, idx);
        float kL = sel4(Kdu, Kdr, Ksu, Ksr, idx);
        float aR = sel4(Adu, Adr, Asu, Asr, jdx);
        float kR = sel4(Kdu, Kdr, Ksu, Ksr, jdx);
        cL = fmaf(aL, kL - cL, cL);  mL = fmaf(-aL, mL, mL);
        cR = fmaf(aR, kR - cR, cR);  mR = fmaf(-aR, mR, mR);
    }

    // ---- warp-level inclusive scan (affine compose, earlier lane first) ----
    #pragma unroll
    for (int d = 1; d < 32; d <<= 1) {
        float pmL = __shfl_up_sync(0xffffffffu, mL, d);
        float pcL = __shfl_up_sync(0xffffffffu, cL, d);
        float pmR = __shfl_up_sync(0xffffffffu, mR, d);
        float pcR = __shfl_up_sync(0xffffffffu, cR, d);
        if (lane >= d) {
            cL = mL * pcL + cL;  mL = mL * pmL;
            cR = mR * pcR + cR;  mR = mR * pmR;
        }
    }
    if (lane == 31) {
        s_wm[0][warp] = mL; s_wc[0][warp] = cL;
        s_wm[1][warp] = mR; s_wc[1][warp] = cR;
    }

    __syncthreads();

    // ---- every thread composes its own warp-exclusive prefix (v0 = 0) ----
    // 4 independent scalar LDS per step: loads hoist, FMA chain stays short
    float pcl = 0.f, pcr = 0.f;
    #pragma unroll
    for (int w = 0; w < NWARPS - 1; ++w) {
        if (w < warp) {
            pcl = s_wm[0][w] * pcl + s_wc[0][w];
            pcr = s_wm[1][w] * pcr + s_wc[1][w];
        }
    }

    // end-of-chunk v for this lane; start-of-chunk = previous lane's end
    float veL = fmaf(mL, pcl, cL);
    float veR = fmaf(mR, pcr, cR);
    float vL = __shfl_up_sync(0xffffffffu, veL, 1);
    float vR = __shfl_up_sync(0xffffffffu, veR, 1);
    if (lane == 0) { vL = pcl; vR = pcr; }

    // ---- phase 2: compute all 24 outputs into registers, then batch stores ----
    float fv[8], fd[8], fe[8];
    #pragma unroll
    for (int t = 0; t < CHUNK; ++t) {
        unsigned idx = (ibits >> (2 * t)) & 3u;
        unsigned jdx = idx ^ 2u;
        float aL = sel4(Adu, Adr, Asu, Asr, idx);
        float kL = sel4(Kdu, Kdr, Ksu, Ksr, idx);
        float aR = sel4(Adu, Adr, Asu, Asr, jdx);
        float kR = sel4(Kdu, Kdr, Ksu, Ksr, jdx);
        float difL = kL - vL, difR = kR - vR;
        float dL = aL * difL, dR = aR * difR;
        fd[2 * t + 0] = difL;  fd[2 * t + 1] = difR;
        fe[2 * t + 0] = dL;    fe[2 * t + 1] = dR;
        vL += dL;  vR += dR;
        fv[2 * t + 0] = vL;    fv[2 * t + 1] = vR;
    }

    const size_t ob = (size_t)sess * NV + (size_t)tid * (CHUNK * 2);
    stg256(out_v + ob,     fv);
    stg256(out_diff + ob,  fd);
    stg256(out_delta + ob, fe);
}

extern "C" void kernel_launch(void* const* d_in, const int* in_sizes, int n_in,
                              void* d_out, int out_size)
{
    const float* inp = (const float*)d_in[0];
    float* out = (float*)d_out;
    const int n_sess = in_sizes[0] / (TRIALS * 3);
    const size_t per = (size_t)n_sess * TRIALS * 2;

    qv_kernel<<<n_sess, NTHREADS>>>(
        inp,
        (const float*)d_in[1], (const float*)d_in[2],
        (const float*)d_in[3], (const float*)d_in[4],
        (const float*)d_in[5], (const float*)d_in[6],
        (const float*)d_in[7], (const float*)d_in[8],
        out, out + per, out + 2 * per);
}